// round 16
// baseline (speedup 1.0000x reference)
#include <cuda_runtime.h>
#include <stdint.h>
#include <math.h>

#define Bz   4
#define Lz   2048
#define Dz   192
#define DIz  384
#define DSz  64
#define DCz  4
#define DRz  12
#define BLz  (Bz*Lz)        // 8192
#define E2z  (2*DIz)        // 768
#define XDBz (DRz+DSz)      // 76
#define TCH  32
#define LCz  512            // L-chunk for scan split
#define NCz  (Lz/LCz)       // 4

// ---- scratch (no allocations allowed; __device__ globals) ----
__device__ float g_h  [BLz*Dz];     // layernormed hidden
__device__ float g_xz [BLz*E2z];    // in-proj output (x | z)
__device__ float g_x  [BLz*DIz];    // post conv+silu
__device__ float g_xdb[BLz*XDBz];   // x-proj output (dt_in | B)
__device__ float g_S  [BLz*DIz];    // inclusive dt-cumsum within L-chunk
__device__ float g_y  [BLz*DIz];    // scan output (local, then corrected+gated)
__device__ float g_hend  [Bz*NCz*DIz*64];   // per-chunk final local state (C-folded)
__device__ float g_hstart[Bz*NCz*DIz*64];   // per-chunk incoming state (C-folded)

__device__ __forceinline__ float warp_sum(float v) {
#pragma unroll
    for (int o = 16; o; o >>= 1) v += __shfl_xor_sync(0xffffffffu, v, o);
    return v;
}

__device__ __forceinline__ uint32_t f2tf32(float f) {
    uint32_t u;
    asm("cvt.rna.tf32.f32 %0, %1;" : "=r"(u) : "f"(f));
    return u;
}

__device__ __forceinline__ void mma_tf32(float* c, const uint32_t* a, const uint32_t* b) {
    asm volatile(
        "mma.sync.aligned.m16n8k8.row.col.f32.tf32.tf32.f32 "
        "{%0,%1,%2,%3}, {%4,%5,%6,%7}, {%8,%9}, {%0,%1,%2,%3};"
        : "+f"(c[0]), "+f"(c[1]), "+f"(c[2]), "+f"(c[3])
        : "r"(a[0]), "r"(a[1]), "r"(a[2]), "r"(a[3]), "r"(b[0]), "r"(b[1]));
}

// ============================================================================
// Kernel 1: residual = residual + hidden ; LayerNorm -> g_h ; residual -> out[1]
// ============================================================================
__global__ __launch_bounds__(256) void k_ln(
    const float* __restrict__ hs, const float* __restrict__ res,
    const float* __restrict__ lw, const float* __restrict__ lb,
    float* __restrict__ out_res)
{
    int warp = (blockIdx.x * blockDim.x + threadIdx.x) >> 5;
    int lane = threadIdx.x & 31;
    if (warp >= BLz) return;
    const float* ph = hs + (size_t)warp * Dz;
    const float* pr = res + (size_t)warp * Dz;
    float v[6];
    float s = 0.f;
#pragma unroll
    for (int j = 0; j < 6; j++) {
        int e = lane + j * 32;
        v[j] = ph[e] + pr[e];
        s += v[j];
    }
    s = warp_sum(s);
    float mu = s * (1.0f / Dz);
    float q = 0.f;
#pragma unroll
    for (int j = 0; j < 6; j++) { float d = v[j] - mu; q += d * d; }
    q = warp_sum(q);
    float rstd = rsqrtf(q * (1.0f / Dz) + 1e-5f);
    float* po = out_res + (size_t)warp * Dz;
    float* phh = g_h + (size_t)warp * Dz;
#pragma unroll
    for (int j = 0; j < 6; j++) {
        int e = lane + j * 32;
        po[e] = v[j];
        phh[e] = (v[j] - mu) * rstd * lw[e] + lb[e];
    }
}

// ============================================================================
// TF32 tensor-core GEMM: C[M,N] = A[M,K] * W[N,K]^T (row-major).
// Block 128x64, BK=16, double-buffered.
// ============================================================================
#define BMt 128
#define BNt 64
#define BKt 16

template<bool FULLN>
__device__ __forceinline__ void gemm_tc(
    const float* __restrict__ A, const float* __restrict__ W,
    float* __restrict__ C, int N, int K)
{
    __shared__ uint32_t As[2][BKt][BMt + 8];
    __shared__ uint32_t Ws[2][BKt][BNt + 8];

    const int tid = threadIdx.x;
    const int m0 = blockIdx.y * BMt;
    const int n0 = blockIdx.x * BNt;
    const int wid = tid >> 5, lane = tid & 31;
    const int warp_m = wid & 3;
    const int warp_n = wid >> 2;
    const int grp = lane >> 2;
    const int tg  = lane & 3;

    const int ar = tid >> 2;
    const int ac = (tid & 3) * 4;
    const float* pA0 = A + (size_t)(m0 + ar) * K + ac;
    const float* pA1 = A + (size_t)(m0 + ar + 64) * K + ac;
    const bool wv = (n0 + ar) < N;
    const float* pW0 = W + (size_t)(n0 + ar) * K + ac;

    float4 ra0, ra1, rw0;
    float acc[2][4][4] = {};

    const int nch = K / BKt;

    ra0 = *(const float4*)(pA0);
    ra1 = *(const float4*)(pA1);
    rw0 = wv ? *(const float4*)(pW0) : make_float4(0.f,0.f,0.f,0.f);
    {
        As[0][ac+0][ar] = f2tf32(ra0.x); As[0][ac+1][ar] = f2tf32(ra0.y);
        As[0][ac+2][ar] = f2tf32(ra0.z); As[0][ac+3][ar] = f2tf32(ra0.w);
        As[0][ac+0][ar+64] = f2tf32(ra1.x); As[0][ac+1][ar+64] = f2tf32(ra1.y);
        As[0][ac+2][ar+64] = f2tf32(ra1.z); As[0][ac+3][ar+64] = f2tf32(ra1.w);
        Ws[0][ac+0][ar] = f2tf32(rw0.x); Ws[0][ac+1][ar] = f2tf32(rw0.y);
        Ws[0][ac+2][ar] = f2tf32(rw0.z); Ws[0][ac+3][ar] = f2tf32(rw0.w);
    }
    __syncthreads();

    for (int c = 0; c < nch; c++) {
        const int cur = c & 1;
        if (c + 1 < nch) {
            int k0 = (c + 1) * BKt;
            ra0 = *(const float4*)(pA0 + k0);
            ra1 = *(const float4*)(pA1 + k0);
            rw0 = wv ? *(const float4*)(pW0 + k0) : make_float4(0.f,0.f,0.f,0.f);
        }
#pragma unroll
        for (int ks = 0; ks < BKt / 8; ks++) {
            const int kb = ks * 8;
            uint32_t a[2][4], b[4][2];
#pragma unroll
            for (int mf = 0; mf < 2; mf++) {
                const int mb = warp_m * 32 + mf * 16;
                a[mf][0] = As[cur][kb + tg    ][mb + grp];
                a[mf][1] = As[cur][kb + tg    ][mb + grp + 8];
                a[mf][2] = As[cur][kb + tg + 4][mb + grp];
                a[mf][3] = As[cur][kb + tg + 4][mb + grp + 8];
            }
#pragma unroll
            for (int nf = 0; nf < 4; nf++) {
                const int nb = warp_n * 32 + nf * 8;
                b[nf][0] = Ws[cur][kb + tg    ][nb + grp];
                b[nf][1] = Ws[cur][kb + tg + 4][nb + grp];
            }
#pragma unroll
            for (int mf = 0; mf < 2; mf++)
#pragma unroll
                for (int nf = 0; nf < 4; nf++)
                    mma_tf32(acc[mf][nf], a[mf], b[nf]);
        }
        if (c + 1 < nch) {
            const int nxt = (c + 1) & 1;
            As[nxt][ac+0][ar] = f2tf32(ra0.x); As[nxt][ac+1][ar] = f2tf32(ra0.y);
            As[nxt][ac+2][ar] = f2tf32(ra0.z); As[nxt][ac+3][ar] = f2tf32(ra0.w);
            As[nxt][ac+0][ar+64] = f2tf32(ra1.x); As[nxt][ac+1][ar+64] = f2tf32(ra1.y);
            As[nxt][ac+2][ar+64] = f2tf32(ra1.z); As[nxt][ac+3][ar+64] = f2tf32(ra1.w);
            Ws[nxt][ac+0][ar] = f2tf32(rw0.x); Ws[nxt][ac+1][ar] = f2tf32(rw0.y);
            Ws[nxt][ac+2][ar] = f2tf32(rw0.z); Ws[nxt][ac+3][ar] = f2tf32(rw0.w);
        }
        __syncthreads();
    }

#pragma unroll
    for (int mf = 0; mf < 2; mf++) {
        const int r0 = m0 + warp_m * 32 + mf * 16 + grp;
#pragma unroll
        for (int nf = 0; nf < 4; nf++) {
            const int col = n0 + warp_n * 32 + nf * 8 + 2 * tg;
            if (FULLN) {
                *(float2*)&C[(size_t)r0 * N + col]       = make_float2(acc[mf][nf][0], acc[mf][nf][1]);
                *(float2*)&C[(size_t)(r0 + 8) * N + col] = make_float2(acc[mf][nf][2], acc[mf][nf][3]);
            } else {
                if (col < N) {
                    C[(size_t)r0 * N + col] = acc[mf][nf][0];
                    C[(size_t)(r0 + 8) * N + col] = acc[mf][nf][2];
                }
                if (col + 1 < N) {
                    C[(size_t)r0 * N + col + 1] = acc[mf][nf][1];
                    C[(size_t)(r0 + 8) * N + col + 1] = acc[mf][nf][3];
                }
            }
        }
    }
}

__global__ __launch_bounds__(256) void k_gemm_xz(const float* __restrict__ Win) {
    gemm_tc<true>(g_h, Win, g_xz, E2z, Dz);
}
__global__ __launch_bounds__(256) void k_gemm_out(const float* __restrict__ Wout, float* __restrict__ out) {
    gemm_tc<true>(g_y, Wout, out, Dz, DIz);
}

// ============================================================================
// FUSED conv+SiLU+xdb GEMM: xdb = silu(conv(xz_x)) @ Wxp^T.
// Writes g_x (n0==0 block) and g_xdb.
// ============================================================================
__global__ __launch_bounds__(256) void k_conv_xdb(
    const float* __restrict__ cw, const float* __restrict__ cb,
    const float* __restrict__ Wxp)
{
    __shared__ uint32_t As[BKt][BMt + 8];
    __shared__ uint32_t Ws[BKt][BNt + 8];

    const int N = XDBz, K = DIz;
    const int tid = threadIdx.x;
    const int m0 = blockIdx.y * BMt;
    const int n0 = blockIdx.x * BNt;
    const int wid = tid >> 5, lane = tid & 31;
    const int warp_m = wid & 3;
    const int warp_n = wid >> 2;
    const int grp = lane >> 2;
    const int tg  = lane & 3;

    const int ar = tid >> 2;
    const int ac = (tid & 3) * 4;
    const bool wv = (n0 + ar) < N;
    const float* pW0 = Wxp + (size_t)(n0 + ar) * K + ac;
    const bool writex = (n0 == 0);

    float acc[2][4][4] = {};

    for (int c = 0; c < K / BKt; c++) {
        const int k0 = c * BKt;
        const int d = k0 + ac;
        float4 wj0 = *(const float4*)(cw + (d + 0) * 4);
        float4 wj1 = *(const float4*)(cw + (d + 1) * 4);
        float4 wj2 = *(const float4*)(cw + (d + 2) * 4);
        float4 wj3 = *(const float4*)(cw + (d + 3) * 4);
        float4 cbv = *(const float4*)(cb + d);
#pragma unroll
        for (int rs = 0; rs < 2; rs++) {
            const int r = m0 + ar + rs * 64;
            const int t = r & (Lz - 1);
            const float* base = g_xz + (size_t)r * E2z + d;
            float4 x3 = *(const float4*)(base);
            float4 x2 = (t >= 1) ? *(const float4*)(base - E2z)     : make_float4(0,0,0,0);
            float4 x1 = (t >= 2) ? *(const float4*)(base - 2 * E2z) : make_float4(0,0,0,0);
            float4 x0 = (t >= 3) ? *(const float4*)(base - 3 * E2z) : make_float4(0,0,0,0);
            float xo[4];
            {
                float s;
                s = cbv.x; s = fmaf(wj0.x, x0.x, s); s = fmaf(wj0.y, x1.x, s); s = fmaf(wj0.z, x2.x, s); s = fmaf(wj0.w, x3.x, s);
                xo[0] = s / (1.f + __expf(-s));
                s = cbv.y; s = fmaf(wj1.x, x0.y, s); s = fmaf(wj1.y, x1.y, s); s = fmaf(wj1.z, x2.y, s); s = fmaf(wj1.w, x3.y, s);
                xo[1] = s / (1.f + __expf(-s));
                s = cbv.z; s = fmaf(wj2.x, x0.z, s); s = fmaf(wj2.y, x1.z, s); s = fmaf(wj2.z, x2.z, s); s = fmaf(wj2.w, x3.z, s);
                xo[2] = s / (1.f + __expf(-s));
                s = cbv.w; s = fmaf(wj3.x, x0.w, s); s = fmaf(wj3.y, x1.w, s); s = fmaf(wj3.z, x2.w, s); s = fmaf(wj3.w, x3.w, s);
                xo[3] = s / (1.f + __expf(-s));
            }
            const int arr = ar + rs * 64;
            As[ac+0][arr] = f2tf32(xo[0]); As[ac+1][arr] = f2tf32(xo[1]);
            As[ac+2][arr] = f2tf32(xo[2]); As[ac+3][arr] = f2tf32(xo[3]);
            if (writex) {
                *(float4*)(g_x + (size_t)r * DIz + d) = make_float4(xo[0], xo[1], xo[2], xo[3]);
            }
        }
        {
            float4 rw0 = wv ? *(const float4*)(pW0 + k0) : make_float4(0,0,0,0);
            Ws[ac+0][ar] = f2tf32(rw0.x); Ws[ac+1][ar] = f2tf32(rw0.y);
            Ws[ac+2][ar] = f2tf32(rw0.z); Ws[ac+3][ar] = f2tf32(rw0.w);
        }
        __syncthreads();

#pragma unroll
        for (int ks = 0; ks < BKt / 8; ks++) {
            const int kb = ks * 8;
            uint32_t a[2][4], b[4][2];
#pragma unroll
            for (int mf = 0; mf < 2; mf++) {
                const int mb = warp_m * 32 + mf * 16;
                a[mf][0] = As[kb + tg    ][mb + grp];
                a[mf][1] = As[kb + tg    ][mb + grp + 8];
                a[mf][2] = As[kb + tg + 4][mb + grp];
                a[mf][3] = As[kb + tg + 4][mb + grp + 8];
            }
#pragma unroll
            for (int nf = 0; nf < 4; nf++) {
                const int nb = warp_n * 32 + nf * 8;
                b[nf][0] = Ws[kb + tg    ][nb + grp];
                b[nf][1] = Ws[kb + tg + 4][nb + grp];
            }
#pragma unroll
            for (int mf = 0; mf < 2; mf++)
#pragma unroll
                for (int nf = 0; nf < 4; nf++)
                    mma_tf32(acc[mf][nf], a[mf], b[nf]);
        }
        __syncthreads();
    }

#pragma unroll
    for (int mf = 0; mf < 2; mf++) {
        const int r0 = m0 + warp_m * 32 + mf * 16 + grp;
#pragma unroll
        for (int nf = 0; nf < 4; nf++) {
            const int col = n0 + warp_n * 32 + nf * 8 + 2 * tg;
            if (col < N) {
                g_xdb[(size_t)r0 * N + col] = acc[mf][nf][0];
                g_xdb[(size_t)(r0 + 8) * N + col] = acc[mf][nf][2];
            }
            if (col + 1 < N) {
                g_xdb[(size_t)r0 * N + col + 1] = acc[mf][nf][1];
                g_xdb[(size_t)(r0 + 8) * N + col + 1] = acc[mf][nf][3];
            }
        }
    }
}

// ============================================================================
// Scan pass A: per (b, channel-pair, L-chunk of 512) local scan from h=0.
// v4 inner loop (2 warps/channel, 32 states each, no shfl reconstruction).
// Writes: y_local (ungated) -> g_y, inclusive dt-cumsum -> g_S,
// chunk-final state -> g_hend. Grid 3072 blocks -> ~full occupancy.
// ============================================================================
__global__ __launch_bounds__(128) void k_scanA(
    const float* __restrict__ Alog, const float* __restrict__ Cf,
    const float* __restrict__ Wdt, const float* __restrict__ bdt)
{
    __shared__ float  sBC[TCH][64];
    __shared__ float2 sDD[2][TCH];
    __shared__ float  sS [2][TCH];
    __shared__ float  sP [2][TCH][17];

    int bx = blockIdx.x;
    int c    = bx % NCz;
    int rem  = bx / NCz;
    int dblk = rem % (DIz / 2);
    int b    = rem / (DIz / 2);
    int tid = threadIdx.x, lane = tid & 31, wid = tid >> 5;
    int dl   = wid >> 1;
    int half = wid & 1;
    int d = dblk * 2 + dl;
    int n = half * 32 + lane;

    const float LOG2E = 1.4426950408889634f;
    float aa = -expf(Alog[d * DSz + n]) * LOG2E;   // = -(n+1)*log2(e)
    float h = 0.f, S = 0.f;
    int rbase = b * Lz + c * LCz;

    const int et  = tid & 31;
    const int edl = tid >> 5;

    for (int sc = 0; sc < LCz / TCH; sc++) {
        int r0 = rbase + sc * TCH;
        // stage B*C tile as float4
#pragma unroll
        for (int k = 0; k < 4; k++) {
            int i = tid + k * 128;
            int t = i >> 4, v = (i & 15) * 4;
            float4 xv = *(const float4*)(g_xdb + (size_t)(r0 + t) * XDBz + DRz + v);
            float4 cf = *(const float4*)(Cf + v);
            sBC[t][v + 0] = xv.x * cf.x;
            sBC[t][v + 1] = xv.y * cf.y;
            sBC[t][v + 2] = xv.z * cf.z;
            sBC[t][v + 3] = xv.w * cf.w;
        }
        // fused dt prep
        if (tid < 64) {
            int rr = r0 + et, dg = dblk * 2 + edl;
            const float* xb = g_xdb + (size_t)rr * XDBz;
            const float* wr = Wdt + dg * 12;
            float4 xb0 = *(const float4*)(xb);
            float4 xb1 = *(const float4*)(xb + 4);
            float4 xb2 = *(const float4*)(xb + 8);
            float4 wr0 = *(const float4*)(wr);
            float4 wr1 = *(const float4*)(wr + 4);
            float4 wr2 = *(const float4*)(wr + 8);
            float s = bdt[dg];
            s = fmaf(xb0.x, wr0.x, s); s = fmaf(xb0.y, wr0.y, s);
            s = fmaf(xb0.z, wr0.z, s); s = fmaf(xb0.w, wr0.w, s);
            s = fmaf(xb1.x, wr1.x, s); s = fmaf(xb1.y, wr1.y, s);
            s = fmaf(xb1.z, wr1.z, s); s = fmaf(xb1.w, wr1.w, s);
            s = fmaf(xb2.x, wr2.x, s); s = fmaf(xb2.y, wr2.y, s);
            s = fmaf(xb2.z, wr2.z, s); s = fmaf(xb2.w, wr2.w, s);
            float sp = (s > 20.f) ? s : log1pf(__expf(s));
            float u = g_x[(size_t)rr * DIz + dg];
            sDD[edl][et] = make_float2(sp, sp * u);
        }
        __syncthreads();

        // batch-8 three-phase recurrence
#pragma unroll
        for (int tb = 0; tb < TCH / 8; tb++) {
            float e[8], q[8], snap[8];
#pragma unroll
            for (int j = 0; j < 8; j++) {
                float2 dd = sDD[dl][tb * 8 + j];
                float bc = sBC[tb * 8 + j][n];
                e[j] = exp2f(dd.x * aa);
                q[j] = dd.y * bc;
                S += dd.x;
                if (half == 0 && lane == 0) sS[dl][tb * 8 + j] = S;
            }
#pragma unroll
            for (int j = 0; j < 8; j++) {
                h = fmaf(e[j], h, q[j]);
                snap[j] = h;
            }
#pragma unroll
            for (int j = 0; j < 8; j++) {
                float p = snap[j];
                p += __shfl_xor_sync(0xffffffffu, p, 16);
                p += __shfl_xor_sync(0xffffffffu, p, 8);
                if (lane < 8) sP[dl][tb * 8 + j][half * 8 + lane] = p;
            }
        }
        __syncthreads();

        // epilogue: ungated y_local + S store
        if (tid < 64) {
            const float* p = sP[edl][et];
            float s0 = p[0] + p[1], s1 = p[2] + p[3];
            float s2 = p[4] + p[5], s3 = p[6] + p[7];
            float s4 = p[8] + p[9], s5 = p[10] + p[11];
            float s6 = p[12] + p[13], s7 = p[14] + p[15];
            int rr = r0 + et, dg = dblk * 2 + edl;
            g_y[(size_t)rr * DIz + dg] = ((s0 + s1) + (s2 + s3)) + ((s4 + s5) + (s6 + s7));
            g_S[(size_t)rr * DIz + dg] = sS[edl][et];
        }
        __syncthreads();
    }

    // chunk-final state
    g_hend[((size_t)((b * NCz + c) * DIz) + d) * 64 + n] = h;
}

// ============================================================================
// Scan pass B: sequential cross-chunk combine (tiny).
// warp = (b,d) channel: hstart[c] = h; h = exp(a*Ssum_c) o h + hend[c].
// ============================================================================
__global__ __launch_bounds__(256) void k_scanB(const float* __restrict__ Alog)
{
    int w = (blockIdx.x * blockDim.x + threadIdx.x) >> 5;
    int lane = threadIdx.x & 31;
    if (w >= Bz * DIz) return;
    int b = w / DIz, d = w % DIz;

    const float LOG2E = 1.4426950408889634f;
    float aa0 = -expf(Alog[d * DSz + lane]) * LOG2E;
    float h0 = 0.f, h1 = 0.f;

#pragma unroll
    for (int c = 0; c < NCz; c++) {
        size_t base = ((size_t)((b * NCz + c) * DIz) + d) * 64;
        g_hstart[base + lane]      = h0;
        g_hstart[base + 32 + lane] = h1;
        float Ssum = g_S[(size_t)(b * Lz + c * LCz + LCz - 1) * DIz + d];
        float D0 = exp2f(Ssum * aa0);
        float w32 = __shfl_sync(0xffffffffu, D0, 31);
        h0 = fmaf(D0, h0, g_hend[base + lane]);
        h1 = fmaf(D0 * w32, h1, g_hend[base + 32 + lane]);
    }
}

// ============================================================================
// Scan pass C: Horner correction + gate.
// Lanes = 32 channels; warp loops 32 t's (2 interleaved chains).
// corr(t,d) = sum_n hs[d][n] * r^(n+1), r = exp(-S_t[d]); Horner: 64 FMA +
// 1 EX2 per (t,d). hs staged in smem [32][65] (conflict-free). Chunk 0: gate only.
// ============================================================================
__global__ __launch_bounds__(128) void k_scanC(const float* __restrict__ Dsk)
{
    __shared__ float sHS[32][65];

    const int NGRP = (Bz * DIz) / 32;   // 48 channel groups
    int bx = blockIdx.x;
    int chgrp = bx % NGRP;
    int tsl4  = bx / NGRP;              // 0..15
    int b   = chgrp / (DIz / 32);
    int dg0 = (chgrp % (DIz / 32)) * 32;
    int tid = threadIdx.x, lane = tid & 31, wid = tid >> 5;
    int t0 = (tsl4 * 4 + wid) * 32;     // warp's 32 t's; all 4 warps same chunk
    int c  = (tsl4 * 128) / LCz;
    int d  = dg0 + lane;

    const float LOG2E = 1.4426950408889634f;

    if (c > 0) {
        for (int i = tid; i < 32 * 64; i += 128) {
            int dd = i >> 6, nn = i & 63;
            sHS[dd][nn] = g_hstart[((size_t)((b * NCz + c) * DIz) + dg0 + dd) * 64 + nn];
        }
    }
    __syncthreads();

    for (int tt = 0; tt < 32; tt += 2) {
        int rr0 = b * Lz + t0 + tt;
        int rr1 = rr0 + 1;
        float corr0 = 0.f, corr1 = 0.f;
        if (c > 0) {
            float S0 = g_S[(size_t)rr0 * DIz + d];
            float S1 = g_S[(size_t)rr1 * DIz + d];
            float ra = exp2f(-S0 * LOG2E);
            float rb = exp2f(-S1 * LOG2E);
#pragma unroll
            for (int nn = 63; nn >= 0; nn--) {
                float hsv = sHS[lane][nn];
                corr0 = fmaf(corr0, ra, hsv);
                corr1 = fmaf(corr1, rb, hsv);
            }
            corr0 *= ra;
            corr1 *= rb;
        }
#pragma unroll
        for (int u = 0; u < 2; u++) {
            int rr = (u == 0) ? rr0 : rr1;
            float corr = (u == 0) ? corr0 : corr1;
            size_t yi = (size_t)rr * DIz + d;
            float xv = g_x[yi];
            float zv = g_xz[(size_t)rr * E2z + DIz + d];
            float y = g_y[yi] + corr + xv * Dsk[d];
            float sig = 1.f / (1.f + __expf(-zv));
            g_y[yi] = y * (zv * sig);
        }
    }
}

// ============================================================================
// launcher — 7 kernels; scanA is launch #4 (profiling lands there)
// ============================================================================
extern "C" void kernel_launch(void* const* d_in, const int* in_sizes, int n_in,
                              void* d_out, int out_size)
{
    (void)in_sizes; (void)n_in; (void)out_size;
    const float* hs   = (const float*)d_in[0];
    const float* res  = (const float*)d_in[1];
    const float* lw   = (const float*)d_in[2];
    const float* lb   = (const float*)d_in[3];
    const float* Win  = (const float*)d_in[4];
    const float* cw   = (const float*)d_in[5];
    const float* cb   = (const float*)d_in[6];
    const float* Wxp  = (const float*)d_in[7];
    const float* Wdt  = (const float*)d_in[8];
    const float* bdt  = (const float*)d_in[9];
    const float* Alog = (const float*)d_in[10];
    const float* Dsk  = (const float*)d_in[11];
    const float* Cf   = (const float*)d_in[12];
    const float* Wout = (const float*)d_in[13];
    float* out = (float*)d_out;
    float* out_res = out + (size_t)BLz * Dz;

    // 1. residual + LN
    k_ln<<<BLz / 8, 256>>>(hs, res, lw, lb, out_res);
    // 2. xz = h @ W_in^T
    { dim3 g(E2z / BNt, BLz / BMt); k_gemm_xz<<<g, 256>>>(Win); }
    // 3. fused conv+silu + xdb GEMM (writes g_x, g_xdb)
    { dim3 g((XDBz + BNt - 1) / BNt, BLz / BMt); k_conv_xdb<<<g, 256>>>(cw, cb, Wxp); }
    // 4-6. chunked scan: local (full occupancy), combine, Horner-correct+gate
    k_scanA<<<Bz * (DIz / 2) * NCz, 128>>>(Alog, Cf, Wdt, bdt);
    k_scanB<<<(Bz * DIz * 32 + 255) / 256, 256>>>(Alog);
    k_scanC<<<((Bz * DIz) / 32) * (Lz / 128), 128>>>(Dsk);
    // 7. out = y @ W_out^T
    { dim3 g(Dz / BNt, BLz / BMt); k_gemm_out<<<g, 256>>>(Wout, out); }
}

// round 17
// speedup vs baseline: 1.2770x; 1.2770x over previous
#include <cuda_runtime.h>
#include <stdint.h>
#include <math.h>

#define Bz   4
#define Lz   2048
#define Dz   192
#define DIz  384
#define DSz  64
#define DCz  4
#define DRz  12
#define BLz  (Bz*Lz)        // 8192
#define E2z  (2*DIz)        // 768
#define XDBz (DRz+DSz)      // 76
#define TCH  32

// ---- scratch (no allocations allowed; __device__ globals) ----
__device__ float g_h  [BLz*Dz];     // layernormed hidden
__device__ float g_xz [BLz*E2z];    // in-proj output (x | z)
__device__ float g_x  [BLz*DIz];    // post conv+silu
__device__ float g_xdb[BLz*XDBz];   // x-proj output (dt_in | B)
__device__ float g_y  [BLz*DIz];    // gated scan output

__device__ __forceinline__ float warp_sum(float v) {
#pragma unroll
    for (int o = 16; o; o >>= 1) v += __shfl_xor_sync(0xffffffffu, v, o);
    return v;
}

__device__ __forceinline__ uint32_t f2tf32(float f) {
    uint32_t u;
    asm("cvt.rna.tf32.f32 %0, %1;" : "=r"(u) : "f"(f));
    return u;
}

__device__ __forceinline__ void mma_tf32(float* c, const uint32_t* a, const uint32_t* b) {
    asm volatile(
        "mma.sync.aligned.m16n8k8.row.col.f32.tf32.tf32.f32 "
        "{%0,%1,%2,%3}, {%4,%5,%6,%7}, {%8,%9}, {%0,%1,%2,%3};"
        : "+f"(c[0]), "+f"(c[1]), "+f"(c[2]), "+f"(c[3])
        : "r"(a[0]), "r"(a[1]), "r"(a[2]), "r"(a[3]), "r"(b[0]), "r"(b[1]));
}

// ============================================================================
// Kernel 1: residual = residual + hidden ; LayerNorm -> g_h ; residual -> out[1]
// ============================================================================
__global__ __launch_bounds__(256) void k_ln(
    const float* __restrict__ hs, const float* __restrict__ res,
    const float* __restrict__ lw, const float* __restrict__ lb,
    float* __restrict__ out_res)
{
    int warp = (blockIdx.x * blockDim.x + threadIdx.x) >> 5;
    int lane = threadIdx.x & 31;
    if (warp >= BLz) return;
    const float* ph = hs + (size_t)warp * Dz;
    const float* pr = res + (size_t)warp * Dz;
    float v[6];
    float s = 0.f;
#pragma unroll
    for (int j = 0; j < 6; j++) {
        int e = lane + j * 32;
        v[j] = ph[e] + pr[e];
        s += v[j];
    }
    s = warp_sum(s);
    float mu = s * (1.0f / Dz);
    float q = 0.f;
#pragma unroll
    for (int j = 0; j < 6; j++) { float d = v[j] - mu; q += d * d; }
    q = warp_sum(q);
    float rstd = rsqrtf(q * (1.0f / Dz) + 1e-5f);
    float* po = out_res + (size_t)warp * Dz;
    float* phh = g_h + (size_t)warp * Dz;
#pragma unroll
    for (int j = 0; j < 6; j++) {
        int e = lane + j * 32;
        po[e] = v[j];
        phh[e] = (v[j] - mu) * rstd * lw[e] + lb[e];
    }
}

// ============================================================================
// TF32 tensor-core GEMM: C[M,N] = A[M,K] * W[N,K]^T (row-major).
// Block 128x64, BK=16, double-buffered.
// ============================================================================
#define BMt 128
#define BNt 64
#define BKt 16

template<bool FULLN>
__device__ __forceinline__ void gemm_tc(
    const float* __restrict__ A, const float* __restrict__ W,
    float* __restrict__ C, int N, int K)
{
    __shared__ uint32_t As[2][BKt][BMt + 8];
    __shared__ uint32_t Ws[2][BKt][BNt + 8];

    const int tid = threadIdx.x;
    const int m0 = blockIdx.y * BMt;
    const int n0 = blockIdx.x * BNt;
    const int wid = tid >> 5, lane = tid & 31;
    const int warp_m = wid & 3;
    const int warp_n = wid >> 2;
    const int grp = lane >> 2;
    const int tg  = lane & 3;

    const int ar = tid >> 2;
    const int ac = (tid & 3) * 4;
    const float* pA0 = A + (size_t)(m0 + ar) * K + ac;
    const float* pA1 = A + (size_t)(m0 + ar + 64) * K + ac;
    const bool wv = (n0 + ar) < N;
    const float* pW0 = W + (size_t)(n0 + ar) * K + ac;

    float4 ra0, ra1, rw0;
    float acc[2][4][4] = {};

    const int nch = K / BKt;

    ra0 = *(const float4*)(pA0);
    ra1 = *(const float4*)(pA1);
    rw0 = wv ? *(const float4*)(pW0) : make_float4(0.f,0.f,0.f,0.f);
    {
        As[0][ac+0][ar] = f2tf32(ra0.x); As[0][ac+1][ar] = f2tf32(ra0.y);
        As[0][ac+2][ar] = f2tf32(ra0.z); As[0][ac+3][ar] = f2tf32(ra0.w);
        As[0][ac+0][ar+64] = f2tf32(ra1.x); As[0][ac+1][ar+64] = f2tf32(ra1.y);
        As[0][ac+2][ar+64] = f2tf32(ra1.z); As[0][ac+3][ar+64] = f2tf32(ra1.w);
        Ws[0][ac+0][ar] = f2tf32(rw0.x); Ws[0][ac+1][ar] = f2tf32(rw0.y);
        Ws[0][ac+2][ar] = f2tf32(rw0.z); Ws[0][ac+3][ar] = f2tf32(rw0.w);
    }
    __syncthreads();

    for (int c = 0; c < nch; c++) {
        const int cur = c & 1;
        if (c + 1 < nch) {
            int k0 = (c + 1) * BKt;
            ra0 = *(const float4*)(pA0 + k0);
            ra1 = *(const float4*)(pA1 + k0);
            rw0 = wv ? *(const float4*)(pW0 + k0) : make_float4(0.f,0.f,0.f,0.f);
        }
#pragma unroll
        for (int ks = 0; ks < BKt / 8; ks++) {
            const int kb = ks * 8;
            uint32_t a[2][4], b[4][2];
#pragma unroll
            for (int mf = 0; mf < 2; mf++) {
                const int mb = warp_m * 32 + mf * 16;
                a[mf][0] = As[cur][kb + tg    ][mb + grp];
                a[mf][1] = As[cur][kb + tg    ][mb + grp + 8];
                a[mf][2] = As[cur][kb + tg + 4][mb + grp];
                a[mf][3] = As[cur][kb + tg + 4][mb + grp + 8];
            }
#pragma unroll
            for (int nf = 0; nf < 4; nf++) {
                const int nb = warp_n * 32 + nf * 8;
                b[nf][0] = Ws[cur][kb + tg    ][nb + grp];
                b[nf][1] = Ws[cur][kb + tg + 4][nb + grp];
            }
#pragma unroll
            for (int mf = 0; mf < 2; mf++)
#pragma unroll
                for (int nf = 0; nf < 4; nf++)
                    mma_tf32(acc[mf][nf], a[mf], b[nf]);
        }
        if (c + 1 < nch) {
            const int nxt = (c + 1) & 1;
            As[nxt][ac+0][ar] = f2tf32(ra0.x); As[nxt][ac+1][ar] = f2tf32(ra0.y);
            As[nxt][ac+2][ar] = f2tf32(ra0.z); As[nxt][ac+3][ar] = f2tf32(ra0.w);
            As[nxt][ac+0][ar+64] = f2tf32(ra1.x); As[nxt][ac+1][ar+64] = f2tf32(ra1.y);
            As[nxt][ac+2][ar+64] = f2tf32(ra1.z); As[nxt][ac+3][ar+64] = f2tf32(ra1.w);
            Ws[nxt][ac+0][ar] = f2tf32(rw0.x); Ws[nxt][ac+1][ar] = f2tf32(rw0.y);
            Ws[nxt][ac+2][ar] = f2tf32(rw0.z); Ws[nxt][ac+3][ar] = f2tf32(rw0.w);
        }
        __syncthreads();
    }

#pragma unroll
    for (int mf = 0; mf < 2; mf++) {
        const int r0 = m0 + warp_m * 32 + mf * 16 + grp;
#pragma unroll
        for (int nf = 0; nf < 4; nf++) {
            const int col = n0 + warp_n * 32 + nf * 8 + 2 * tg;
            if (FULLN) {
                *(float2*)&C[(size_t)r0 * N + col]       = make_float2(acc[mf][nf][0], acc[mf][nf][1]);
                *(float2*)&C[(size_t)(r0 + 8) * N + col] = make_float2(acc[mf][nf][2], acc[mf][nf][3]);
            } else {
                if (col < N) {
                    C[(size_t)r0 * N + col] = acc[mf][nf][0];
                    C[(size_t)(r0 + 8) * N + col] = acc[mf][nf][2];
                }
                if (col + 1 < N) {
                    C[(size_t)r0 * N + col + 1] = acc[mf][nf][1];
                    C[(size_t)(r0 + 8) * N + col + 1] = acc[mf][nf][3];
                }
            }
        }
    }
}

__global__ __launch_bounds__(256) void k_gemm_xz(const float* __restrict__ Win) {
    gemm_tc<true>(g_h, Win, g_xz, E2z, Dz);
}
__global__ __launch_bounds__(256) void k_gemm_out(const float* __restrict__ Wout, float* __restrict__ out) {
    gemm_tc<true>(g_y, Wout, out, Dz, DIz);
}

// ============================================================================
// FUSED conv+SiLU+xdb GEMM: xdb = silu(conv(xz_x)) @ Wxp^T.
// Writes g_x (n0==0 block) and g_xdb.
// ============================================================================
__global__ __launch_bounds__(256) void k_conv_xdb(
    const float* __restrict__ cw, const float* __restrict__ cb,
    const float* __restrict__ Wxp)
{
    __shared__ uint32_t As[BKt][BMt + 8];
    __shared__ uint32_t Ws[BKt][BNt + 8];

    const int N = XDBz, K = DIz;
    const int tid = threadIdx.x;
    const int m0 = blockIdx.y * BMt;
    const int n0 = blockIdx.x * BNt;
    const int wid = tid >> 5, lane = tid & 31;
    const int warp_m = wid & 3;
    const int warp_n = wid >> 2;
    const int grp = lane >> 2;
    const int tg  = lane & 3;

    const int ar = tid >> 2;
    const int ac = (tid & 3) * 4;
    const bool wv = (n0 + ar) < N;
    const float* pW0 = Wxp + (size_t)(n0 + ar) * K + ac;
    const bool writex = (n0 == 0);

    float acc[2][4][4] = {};

    for (int c = 0; c < K / BKt; c++) {
        const int k0 = c * BKt;
        const int d = k0 + ac;
        float4 wj0 = *(const float4*)(cw + (d + 0) * 4);
        float4 wj1 = *(const float4*)(cw + (d + 1) * 4);
        float4 wj2 = *(const float4*)(cw + (d + 2) * 4);
        float4 wj3 = *(const float4*)(cw + (d + 3) * 4);
        float4 cbv = *(const float4*)(cb + d);
#pragma unroll
        for (int rs = 0; rs < 2; rs++) {
            const int r = m0 + ar + rs * 64;
            const int t = r & (Lz - 1);
            const float* base = g_xz + (size_t)r * E2z + d;
            float4 x3 = *(const float4*)(base);
            float4 x2 = (t >= 1) ? *(const float4*)(base - E2z)     : make_float4(0,0,0,0);
            float4 x1 = (t >= 2) ? *(const float4*)(base - 2 * E2z) : make_float4(0,0,0,0);
            float4 x0 = (t >= 3) ? *(const float4*)(base - 3 * E2z) : make_float4(0,0,0,0);
            float xo[4];
            {
                float s;
                s = cbv.x; s = fmaf(wj0.x, x0.x, s); s = fmaf(wj0.y, x1.x, s); s = fmaf(wj0.z, x2.x, s); s = fmaf(wj0.w, x3.x, s);
                xo[0] = s / (1.f + __expf(-s));
                s = cbv.y; s = fmaf(wj1.x, x0.y, s); s = fmaf(wj1.y, x1.y, s); s = fmaf(wj1.z, x2.y, s); s = fmaf(wj1.w, x3.y, s);
                xo[1] = s / (1.f + __expf(-s));
                s = cbv.z; s = fmaf(wj2.x, x0.z, s); s = fmaf(wj2.y, x1.z, s); s = fmaf(wj2.z, x2.z, s); s = fmaf(wj2.w, x3.z, s);
                xo[2] = s / (1.f + __expf(-s));
                s = cbv.w; s = fmaf(wj3.x, x0.w, s); s = fmaf(wj3.y, x1.w, s); s = fmaf(wj3.z, x2.w, s); s = fmaf(wj3.w, x3.w, s);
                xo[3] = s / (1.f + __expf(-s));
            }
            const int arr = ar + rs * 64;
            As[ac+0][arr] = f2tf32(xo[0]); As[ac+1][arr] = f2tf32(xo[1]);
            As[ac+2][arr] = f2tf32(xo[2]); As[ac+3][arr] = f2tf32(xo[3]);
            if (writex) {
                *(float4*)(g_x + (size_t)r * DIz + d) = make_float4(xo[0], xo[1], xo[2], xo[3]);
            }
        }
        {
            float4 rw0 = wv ? *(const float4*)(pW0 + k0) : make_float4(0,0,0,0);
            Ws[ac+0][ar] = f2tf32(rw0.x); Ws[ac+1][ar] = f2tf32(rw0.y);
            Ws[ac+2][ar] = f2tf32(rw0.z); Ws[ac+3][ar] = f2tf32(rw0.w);
        }
        __syncthreads();

#pragma unroll
        for (int ks = 0; ks < BKt / 8; ks++) {
            const int kb = ks * 8;
            uint32_t a[2][4], b[4][2];
#pragma unroll
            for (int mf = 0; mf < 2; mf++) {
                const int mb = warp_m * 32 + mf * 16;
                a[mf][0] = As[kb + tg    ][mb + grp];
                a[mf][1] = As[kb + tg    ][mb + grp + 8];
                a[mf][2] = As[kb + tg + 4][mb + grp];
                a[mf][3] = As[kb + tg + 4][mb + grp + 8];
            }
#pragma unroll
            for (int nf = 0; nf < 4; nf++) {
                const int nb = warp_n * 32 + nf * 8;
                b[nf][0] = Ws[kb + tg    ][nb + grp];
                b[nf][1] = Ws[kb + tg + 4][nb + grp];
            }
#pragma unroll
            for (int mf = 0; mf < 2; mf++)
#pragma unroll
                for (int nf = 0; nf < 4; nf++)
                    mma_tf32(acc[mf][nf], a[mf], b[nf]);
        }
        __syncthreads();
    }

#pragma unroll
    for (int mf = 0; mf < 2; mf++) {
        const int r0 = m0 + warp_m * 32 + mf * 16 + grp;
#pragma unroll
        for (int nf = 0; nf < 4; nf++) {
            const int col = n0 + warp_n * 32 + nf * 8 + 2 * tg;
            if (col < N) {
                g_xdb[(size_t)r0 * N + col] = acc[mf][nf][0];
                g_xdb[(size_t)(r0 + 8) * N + col] = acc[mf][nf][2];
            }
            if (col + 1 < N) {
                g_xdb[(size_t)r0 * N + col + 1] = acc[mf][nf][1];
                g_xdb[(size_t)(r0 + 8) * N + col + 1] = acc[mf][nf][3];
            }
        }
    }
}

// ============================================================================
// Selective scan v5: monolithic (R13 structure), DOUBLE-BUFFERED staging.
// warp = one (b,d) channel; lane holds states n=lane, n=lane+32 (C folded in).
// While computing chunk c, chunk c+1's B*C tile + dt are loaded into the other
// buffer (LDG latency overlapped; 2 syncs/chunk). Two EX2 per step (no SHFL
// in phase 1 -> less MIO pressure). Batch-8 two-phase recurrence; per-lane
// partial to sP; epilogue sums 32 partials + gate.
// ============================================================================
__global__ __launch_bounds__(128) void k_scan(
    const float* __restrict__ Alog, const float* __restrict__ Cf,
    const float* __restrict__ Dsk,
    const float* __restrict__ Wdt, const float* __restrict__ bdt)
{
    __shared__ float2 sBC[2][TCH][32];
    __shared__ float2 sDD[2][4][TCH];
    __shared__ float  sX [2][4][TCH];
    __shared__ float  sP [4][TCH][33];

    int b    = blockIdx.x / (DIz / 4);
    int dblk = blockIdx.x % (DIz / 4);
    int tid = threadIdx.x, lane = tid & 31, wid = tid >> 5;
    int d = dblk * 4 + wid;

    const float LOG2E = 1.4426950408889634f;
    float aa0 = -expf(Alog[d * DSz + lane])      * LOG2E;  // = -(lane+1)*log2e
    float aa1 = -expf(Alog[d * DSz + lane + 32]) * LOG2E;  // = -(lane+33)*log2e
    float h0 = 0.f, h1 = 0.f;
    int rbase = b * Lz;

    const int et  = tid & 31;     // staging/epilogue t
    const int edl = tid >> 5;     // staging/epilogue d-lane

    // ---- staging helper (as a lambda-free macro-style block) ----
    // BC: 4 x float4 per thread (vectorized; (r)*76+12 is 0 mod 4)
    // dt: tid<64 threads each compute one (edl2, et2) pair... use 128 threads:
    //     tid 0..127 -> (dl = tid>>5, t = tid&31) covers 4x32.
#define STAGE_CHUNK(BUF, R0)                                                     \
    {                                                                            \
        _Pragma("unroll")                                                        \
        for (int kk = 0; kk < 4; kk++) {                                         \
            int i = tid + kk * 128;                                              \
            int t = i >> 4, v = (i & 15) * 4;                                    \
            float4 xv = *(const float4*)(g_xdb + (size_t)((R0) + t) * XDBz + DRz + v); \
            float4 cf = *(const float4*)(Cf + v);                                \
            float* row = (float*)&sBC[BUF][t][0];                                \
            row[(v & 31) * 2 + (v >> 5) + 0] = xv.x * cf.x;                      \
            row[((v+1) & 31) * 2 + ((v+1) >> 5)] = xv.y * cf.y;                  \
            row[((v+2) & 31) * 2 + ((v+2) >> 5)] = xv.z * cf.z;                  \
            row[((v+3) & 31) * 2 + ((v+3) >> 5)] = xv.w * cf.w;                  \
        }                                                                        \
        {                                                                        \
            int rr = (R0) + et, dg = dblk * 4 + edl;                             \
            const float* xb = g_xdb + (size_t)rr * XDBz;                         \
            const float* wr = Wdt + dg * 12;                                     \
            float4 xb0 = *(const float4*)(xb);                                   \
            float4 xb1 = *(const float4*)(xb + 4);                               \
            float4 xb2 = *(const float4*)(xb + 8);                               \
            float4 wr0 = *(const float4*)(wr);                                   \
            float4 wr1 = *(const float4*)(wr + 4);                               \
            float4 wr2 = *(const float4*)(wr + 8);                               \
            float s = bdt[dg];                                                   \
            s = fmaf(xb0.x, wr0.x, s); s = fmaf(xb0.y, wr0.y, s);                \
            s = fmaf(xb0.z, wr0.z, s); s = fmaf(xb0.w, wr0.w, s);                \
            s = fmaf(xb1.x, wr1.x, s); s = fmaf(xb1.y, wr1.y, s);                \
            s = fmaf(xb1.z, wr1.z, s); s = fmaf(xb1.w, wr1.w, s);                \
            s = fmaf(xb2.x, wr2.x, s); s = fmaf(xb2.y, wr2.y, s);                \
            s = fmaf(xb2.z, wr2.z, s); s = fmaf(xb2.w, wr2.w, s);                \
            float sp = (s > 20.f) ? s : log1pf(__expf(s));                       \
            float u = g_x[(size_t)rr * DIz + dg];                                \
            sDD[BUF][edl][et] = make_float2(sp, sp * u);                         \
            sX[BUF][edl][et] = u;                                                \
        }                                                                        \
    }

    // prologue: stage chunk 0
    STAGE_CHUNK(0, rbase)
    __syncthreads();

    const int NCHK = Lz / TCH;   // 64
    for (int c = 0; c < NCHK; c++) {
        const int cur = c & 1;
        int r0 = rbase + c * TCH;

        // stage next chunk into the other buffer (overlaps with compute)
        if (c + 1 < NCHK) {
            STAGE_CHUNK(cur ^ 1, r0 + TCH)
        }

        // batch-8 two-phase recurrence (2 EX2/step, no SHFL)
#pragma unroll
        for (int tb = 0; tb < TCH / 8; tb++) {
            float dA0[8], dA1[8], q0[8], q1[8];
#pragma unroll
            for (int j = 0; j < 8; j++) {
                float2 dd = sDD[cur][wid][tb * 8 + j];
                float2 bc = sBC[cur][tb * 8 + j][lane];
                dA0[j] = exp2f(dd.x * aa0);
                dA1[j] = exp2f(dd.x * aa1);
                q0[j] = dd.y * bc.x;
                q1[j] = dd.y * bc.y;
            }
#pragma unroll
            for (int j = 0; j < 8; j++) {
                h0 = fmaf(dA0[j], h0, q0[j]);
                h1 = fmaf(dA1[j], h1, q1[j]);
                sP[wid][tb * 8 + j][lane] = h0 + h1;
            }
        }
        __syncthreads();

        // epilogue: 32-wide sum + y = (scan + x*D_skip)*silu(z)
        {
            const float* p = sP[edl][et];
            float s0 = 0.f, s1 = 0.f, s2 = 0.f, s3 = 0.f;
#pragma unroll
            for (int k = 0; k < 32; k += 4) {
                s0 += p[k]; s1 += p[k + 1]; s2 += p[k + 2]; s3 += p[k + 3];
            }
            float yscan = (s0 + s1) + (s2 + s3);
            int rr = r0 + et, dg = dblk * 4 + edl;
            float xv = sX[cur][edl][et];
            float zv = g_xz[(size_t)rr * E2z + DIz + dg];
            float y = yscan + xv * Dsk[dg];
            float sig = 1.f / (1.f + __expf(-zv));
            g_y[(size_t)rr * DIz + dg] = y * (zv * sig);
        }
        __syncthreads();   // sP free + next buffer's STS visible
    }
#undef STAGE_CHUNK
}

// ============================================================================
// launcher — 5 kernels; scan is launch #4 (profiling lands there)
// ============================================================================
extern "C" void kernel_launch(void* const* d_in, const int* in_sizes, int n_in,
                              void* d_out, int out_size)
{
    (void)in_sizes; (void)n_in; (void)out_size;
    const float* hs   = (const float*)d_in[0];
    const float* res  = (const float*)d_in[1];
    const float* lw   = (const float*)d_in[2];
    const float* lb   = (const float*)d_in[3];
    const float* Win  = (const float*)d_in[4];
    const float* cw   = (const float*)d_in[5];
    const float* cb   = (const float*)d_in[6];
    const float* Wxp  = (const float*)d_in[7];
    const float* Wdt  = (const float*)d_in[8];
    const float* bdt  = (const float*)d_in[9];
    const float* Alog = (const float*)d_in[10];
    const float* Dsk  = (const float*)d_in[11];
    const float* Cf   = (const float*)d_in[12];
    const float* Wout = (const float*)d_in[13];
    float* out = (float*)d_out;
    float* out_res = out + (size_t)BLz * Dz;

    // 1. residual + LN
    k_ln<<<BLz / 8, 256>>>(hs, res, lw, lb, out_res);
    // 2. xz = h @ W_in^T
    { dim3 g(E2z / BNt, BLz / BMt); k_gemm_xz<<<g, 256>>>(Win); }
    // 3. fused conv+silu + xdb GEMM (writes g_x, g_xdb)
    { dim3 g((XDBz + BNt - 1) / BNt, BLz / BMt); k_conv_xdb<<<g, 256>>>(cw, cb, Wxp); }
    // 4. selective scan (double-buffered staging, fused dt prep + gate)
    k_scan<<<Bz * (DIz / 4), 128>>>(Alog, Cf, Dsk, Wdt, bdt);
    // 5. out = y @ W_out^T
    { dim3 g(Dz / BNt, BLz / BMt); k_gemm_out<<<g, 256>>>(Wout, out); }
}